// round 6
// baseline (speedup 1.0000x reference)
#include <cuda_runtime.h>
#include <cuda_bf16.h>
#include <cstdint>

// ============================================================================
// Problem constants
// ============================================================================
#define M_TOTAL 16384   // 8 * 2048
#define IN_F    4096    // K
#define OUT_F   4096    // N

// GEMM tiling (sm_80-style HMMA pipeline; sm_103a-only instrs are unavailable
// because the harness compiles through compute_103 base target)
#define BM 128
#define BN 128
#define BK 64
#define STAGES 4
#define K_ITERS (IN_F / BK)               // 64

#define A_TILE_BYTES (BM * BK * 2)        // 16384 (one limb)
#define STAGE_BYTES  (3 * A_TILE_BYTES)   // Ahi + Alo + B = 49152
#define SMEM_BYTES   (STAGES * STAGE_BYTES) // 196608

// ============================================================================
// Scratch (device globals — no allocation allowed anywhere)
// ============================================================================
__device__ __nv_bfloat16 g_xhi[(size_t)M_TOTAL * IN_F];   // 128 MB
__device__ __nv_bfloat16 g_xlo[(size_t)M_TOTAL * IN_F];   // 128 MB
__device__ __nv_bfloat16 g_sgn[(size_t)OUT_F * IN_F];     // 32 MB
__device__ float         g_scale[OUT_F];

// ============================================================================
// PTX helpers (all sm_80/sm_90 base-target instructions only)
// ============================================================================
__device__ __forceinline__ uint32_t smem_to_u32(const void* p) {
    uint32_t a;
    asm("{ .reg .u64 t; cvta.to.shared.u64 t, %1; cvt.u32.u64 %0, t; }"
        : "=r"(a) : "l"(p));
    return a;
}

__device__ __forceinline__ void cp_async16(uint32_t dst, const void* src) {
    asm volatile("cp.async.cg.shared.global [%0], [%1], 16;"
                 :: "r"(dst), "l"(src) : "memory");
}
#define CP_COMMIT()  asm volatile("cp.async.commit_group;" ::: "memory")
#define CP_WAIT(n)   asm volatile("cp.async.wait_group %0;" :: "n"(n) : "memory")

__device__ __forceinline__ void ldsm4(uint32_t* r, uint32_t addr) {
    asm volatile("ldmatrix.sync.aligned.m8n8.x4.shared.b16 {%0,%1,%2,%3}, [%4];"
                 : "=r"(r[0]), "=r"(r[1]), "=r"(r[2]), "=r"(r[3]) : "r"(addr));
}

__device__ __forceinline__ void mma16816(float* d, const uint32_t* a,
                                         uint32_t b0, uint32_t b1) {
    asm volatile(
        "mma.sync.aligned.m16n8k16.row.col.f32.bf16.bf16.f32 "
        "{%0,%1,%2,%3}, {%4,%5,%6,%7}, {%8,%9}, {%0,%1,%2,%3};"
        : "+f"(d[0]), "+f"(d[1]), "+f"(d[2]), "+f"(d[3])
        : "r"(a[0]), "r"(a[1]), "r"(a[2]), "r"(a[3]), "r"(b0), "r"(b1));
}

// ============================================================================
// Preprocess: W -> sign (bf16 +-1/0) + per-row scale (mean |w|)
// ============================================================================
__global__ void __launch_bounds__(256)
prep_w_kernel(const float* __restrict__ w,
              __nv_bfloat16* __restrict__ sgn,
              float* __restrict__ scale) {
    const int o = blockIdx.x;
    const int tid = threadIdx.x;
    const float4* wr = reinterpret_cast<const float4*>(w + (size_t)o * IN_F);
    __nv_bfloat162* sr = reinterpret_cast<__nv_bfloat162*>(sgn + (size_t)o * IN_F);

    const __nv_bfloat16 P1 = __float2bfloat16(1.0f);
    const __nv_bfloat16 M1 = __float2bfloat16(-1.0f);
    const __nv_bfloat16 Z0 = __float2bfloat16(0.0f);

    float acc = 0.0f;
    for (int i = tid; i < IN_F / 4; i += 256) {
        float4 v = wr[i];
        acc += fabsf(v.x) + fabsf(v.y) + fabsf(v.z) + fabsf(v.w);
        __nv_bfloat16 s0 = (v.x > 0.f) ? P1 : ((v.x < 0.f) ? M1 : Z0);
        __nv_bfloat16 s1 = (v.y > 0.f) ? P1 : ((v.y < 0.f) ? M1 : Z0);
        __nv_bfloat16 s2 = (v.z > 0.f) ? P1 : ((v.z < 0.f) ? M1 : Z0);
        __nv_bfloat16 s3 = (v.w > 0.f) ? P1 : ((v.w < 0.f) ? M1 : Z0);
        sr[2 * i]     = __halves2bfloat162(s0, s1);
        sr[2 * i + 1] = __halves2bfloat162(s2, s3);
    }

    __shared__ float red[256];
    red[tid] = acc;
    __syncthreads();
    #pragma unroll
    for (int off = 128; off > 0; off >>= 1) {
        if (tid < off) red[tid] += red[tid + off];
        __syncthreads();
    }
    if (tid == 0) scale[o] = red[0] * (1.0f / (float)IN_F);
}

// ============================================================================
// Preprocess: x (fp32) -> x_hi + x_lo (two bf16 limbs, exact to ~2^-17)
// ============================================================================
__global__ void __launch_bounds__(256)
prep_x_kernel(const float4* __restrict__ x,
              __nv_bfloat162* __restrict__ xhi,
              __nv_bfloat162* __restrict__ xlo) {
    size_t idx = (size_t)blockIdx.x * 256 + threadIdx.x;
    float4 v = x[idx];
    __nv_bfloat16 h0 = __float2bfloat16(v.x);
    __nv_bfloat16 h1 = __float2bfloat16(v.y);
    __nv_bfloat16 h2 = __float2bfloat16(v.z);
    __nv_bfloat16 h3 = __float2bfloat16(v.w);
    __nv_bfloat16 l0 = __float2bfloat16(v.x - __bfloat162float(h0));
    __nv_bfloat16 l1 = __float2bfloat16(v.y - __bfloat162float(h1));
    __nv_bfloat16 l2 = __float2bfloat16(v.z - __bfloat162float(h2));
    __nv_bfloat16 l3 = __float2bfloat16(v.w - __bfloat162float(h3));
    xhi[2 * idx]     = __halves2bfloat162(h0, h1);
    xhi[2 * idx + 1] = __halves2bfloat162(h2, h3);
    xlo[2 * idx]     = __halves2bfloat162(l0, l1);
    xlo[2 * idx + 1] = __halves2bfloat162(l2, l3);
}

// ============================================================================
// Main GEMM: out[m,n] = scale[n] * sum_k (xhi+xlo)[m,k]*sgn[n,k] + bias[n]
//   cp.async 4-stage pipeline, SW128 XOR-swizzled smem, ldmatrix + HMMA 16816.
//   8 warps: 4(M) x 2(N); warp tile 32x64; B fragments shared across limbs.
// ============================================================================
__global__ void __launch_bounds__(256, 1)
hgemm_kernel(const float* __restrict__ bias, float* __restrict__ out) {
    extern __shared__ __align__(1024) char smem[];
    const uint32_t sb = smem_to_u32(smem);

    const int tid  = threadIdx.x;
    const int lane = tid & 31;
    const int warp = tid >> 5;
    const int wm = warp & 3;          // 0..3  (M strips of 32)
    const int wn = warp >> 2;         // 0..1  (N strips of 64)

    const int m0 = blockIdx.y * BM;
    const int n0 = blockIdx.x * BN;

    // ---- gmem source rows for cp.async (each thread: 16B chunk, 4 rows/tensor)
    const int lrow = tid >> 3;        // 0..31
    const int lch  = tid & 7;         // 0..7 (16B chunk within 128B row)
    const __nv_bfloat16* Ah = g_xhi + (size_t)m0 * IN_F;
    const __nv_bfloat16* Al = g_xlo + (size_t)m0 * IN_F;
    const __nv_bfloat16* Bp = g_sgn + (size_t)n0 * IN_F;

    // ---- ldmatrix per-thread address components (SW128: chunk ^= row&7)
    const int rA    = lane & 15;          // A matrix row within m16 tile
    const int halfA = lane >> 4;          // which 16B k-chunk
    const uint32_t aRowOff = (uint32_t)(wm * 32 + rA) * 128;
    const int swA = rA & 7;

    const int grp = lane >> 3;
    const int l8  = lane & 7;
    const int rB  = wn * 64 + ((grp >> 1) << 3) + l8;  // B (n) row
    const int halfB = grp & 1;
    const uint32_t bRowOff = (uint32_t)rB * 128;
    const int swB = rB & 7;

    float acc[2][8][4];
    #pragma unroll
    for (int t = 0; t < 2; t++)
        #pragma unroll
        for (int j = 0; j < 8; j++)
            #pragma unroll
            for (int r = 0; r < 4; r++) acc[t][j][r] = 0.0f;

    // ---- stage loader -------------------------------------------------------
    auto load_stage = [&](int s, int ki) {
        const int k0 = ki * BK;
        const uint32_t so = sb + (uint32_t)s * STAGE_BYTES;
        #pragma unroll
        for (int r = 0; r < 4; r++) {
            const int row = lrow + 32 * r;
            const size_t go = (size_t)row * IN_F + k0 + lch * 8;
            const uint32_t sw = (uint32_t)row * 128 +
                                (uint32_t)((lch ^ (row & 7)) << 4);
            cp_async16(so + sw,                    Ah + go);
            cp_async16(so + A_TILE_BYTES + sw,     Al + go);
            cp_async16(so + 2 * A_TILE_BYTES + sw, Bp + go);
        }
    };

    // ---- prologue: fill STAGES-1 stages ----
    #pragma unroll
    for (int s = 0; s < STAGES - 1; s++) {
        load_stage(s, s);
        CP_COMMIT();
    }

    // ---- mainloop ----
    for (int i = 0; i < K_ITERS; i++) {
        CP_WAIT(STAGES - 2);      // stage i's group complete
        __syncthreads();          // also: all warps done with stage being refilled

        const int nld = i + STAGES - 1;
        if (nld < K_ITERS) load_stage(nld % STAGES, nld);
        CP_COMMIT();

        const uint32_t so  = sb + (uint32_t)(i % STAGES) * STAGE_BYTES;
        const uint32_t aHi = so;
        const uint32_t aLo = so + A_TILE_BYTES;
        const uint32_t bB  = so + 2 * A_TILE_BYTES;

        #pragma unroll
        for (int kk = 0; kk < 4; kk++) {
            const int c = kk * 2;

            // B fragments: 4 x ldmatrix.x4 -> 8 n8-tiles (shared across limbs)
            uint32_t bf[4][4];
            #pragma unroll
            for (int j = 0; j < 4; j++) {
                uint32_t addr = bB + bRowOff + (uint32_t)j * 2048 +
                                (uint32_t)((((c + halfB) ^ swB)) << 4);
                ldsm4(bf[j], addr);
            }

            // A fragments: 2 limbs x 2 m16-tiles
            uint32_t af[2][2][4];
            #pragma unroll
            for (int t = 0; t < 2; t++) {
                uint32_t sw16 = (uint32_t)(((c + halfA) ^ swA) << 4);
                ldsm4(af[0][t], aHi + aRowOff + (uint32_t)t * 2048 + sw16);
                ldsm4(af[1][t], aLo + aRowOff + (uint32_t)t * 2048 + sw16);
            }

            // 32 HMMAs
            #pragma unroll
            for (int l = 0; l < 2; l++)
                #pragma unroll
                for (int t = 0; t < 2; t++)
                    #pragma unroll
                    for (int j = 0; j < 4; j++) {
                        mma16816(acc[t][2 * j],     af[l][t], bf[j][0], bf[j][1]);
                        mma16816(acc[t][2 * j + 1], af[l][t], bf[j][2], bf[j][3]);
                    }
        }
    }

    // ---- epilogue: y = scale[n]*acc + bias[n], float2 stores ----
    const int gm  = m0 + wm * 32 + (lane >> 2);
    const int gn0 = n0 + wn * 64 + (lane & 3) * 2;
    #pragma unroll
    for (int t = 0; t < 2; t++) {
        const int r0 = gm + t * 16;
        #pragma unroll
        for (int j = 0; j < 8; j++) {
            const int n = gn0 + j * 8;
            const float2 sc = *reinterpret_cast<const float2*>(g_scale + n);
            const float2 bi = *reinterpret_cast<const float2*>(bias + n);
            float2 v0, v1;
            v0.x = acc[t][j][0] * sc.x + bi.x;
            v0.y = acc[t][j][1] * sc.y + bi.y;
            v1.x = acc[t][j][2] * sc.x + bi.x;
            v1.y = acc[t][j][3] * sc.y + bi.y;
            *reinterpret_cast<float2*>(out + (size_t)r0 * OUT_F + n)       = v0;
            *reinterpret_cast<float2*>(out + (size_t)(r0 + 8) * OUT_F + n) = v1;
        }
    }
}

// ============================================================================
// Host side
// ============================================================================
extern "C" void kernel_launch(void* const* d_in, const int* in_sizes, int n_in,
                              void* d_out, int out_size) {
    const float* x    = (const float*)d_in[0];
    const float* w    = (const float*)d_in[1];
    const float* bias = (const float*)d_in[2];
    float* out = (float*)d_out;

    void *pxhi = nullptr, *pxlo = nullptr, *psgn = nullptr, *pscale = nullptr;
    cudaGetSymbolAddress(&pxhi, g_xhi);
    cudaGetSymbolAddress(&pxlo, g_xlo);
    cudaGetSymbolAddress(&psgn, g_sgn);
    cudaGetSymbolAddress(&pscale, g_scale);
    (void)pxhi; (void)pxlo; (void)psgn; (void)pscale;

    // Preprocess
    prep_w_kernel<<<OUT_F, 256>>>(w, (__nv_bfloat16*)psgn, (float*)pscale);
    {
        size_t n4 = ((size_t)M_TOTAL * IN_F) / 4;
        prep_x_kernel<<<(unsigned)(n4 / 256), 256>>>(
            (const float4*)x, (__nv_bfloat162*)pxhi, (__nv_bfloat162*)pxlo);
    }

    // Main GEMM
    static bool attr_set = false;
    cudaFuncSetAttribute(hgemm_kernel,
                         cudaFuncAttributeMaxDynamicSharedMemorySize, SMEM_BYTES);
    (void)attr_set;

    dim3 grid(OUT_F / BN, M_TOTAL / BM);   // (32, 128)
    hgemm_kernel<<<grid, 256, SMEM_BYTES>>>(bias, out);
}

// round 7
// speedup vs baseline: 1.9427x; 1.9427x over previous
#include <cuda_runtime.h>
#include <cuda_fp16.h>
#include <cstdint>

// ============================================================================
// Problem constants
// ============================================================================
#define M_TOTAL 16384   // 8 * 2048
#define IN_F    4096    // K
#define OUT_F   4096    // N

// GEMM tiling — single-limb fp16 HMMA pipeline.
// (tcgen05 is unusable: harness compiles through compute_103 base target,
//  which rejects tcgen05.ld/wait — no way to read TMEM accumulators.)
#define BM 128
#define BN 128
#define BK 64
#define STAGES 3
#define K_ITERS (IN_F / BK)               // 64

#define A_TILE_BYTES (BM * BK * 2)        // 16384
#define STAGE_BYTES  (2 * A_TILE_BYTES)   // A + B = 32768
#define SMEM_BYTES   (STAGES * STAGE_BYTES) // 98304 -> 2 CTAs/SM

// ============================================================================
// Scratch (device globals — no allocation allowed anywhere)
// ============================================================================
__device__ __half g_xh [(size_t)M_TOTAL * IN_F];   // 128 MB
__device__ __half g_sgn[(size_t)OUT_F * IN_F];     // 32 MB
__device__ float  g_scale[OUT_F];

// ============================================================================
// PTX helpers (sm_80 base-target instructions only)
// ============================================================================
__device__ __forceinline__ uint32_t smem_to_u32(const void* p) {
    uint32_t a;
    asm("{ .reg .u64 t; cvta.to.shared.u64 t, %1; cvt.u32.u64 %0, t; }"
        : "=r"(a) : "l"(p));
    return a;
}

__device__ __forceinline__ void cp_async16(uint32_t dst, const void* src) {
    asm volatile("cp.async.cg.shared.global [%0], [%1], 16;"
                 :: "r"(dst), "l"(src) : "memory");
}
#define CP_COMMIT()  asm volatile("cp.async.commit_group;" ::: "memory")
#define CP_WAIT(n)   asm volatile("cp.async.wait_group %0;" :: "n"(n) : "memory")

__device__ __forceinline__ void ldsm4(uint32_t* r, uint32_t addr) {
    asm volatile("ldmatrix.sync.aligned.m8n8.x4.shared.b16 {%0,%1,%2,%3}, [%4];"
                 : "=r"(r[0]), "=r"(r[1]), "=r"(r[2]), "=r"(r[3]) : "r"(addr));
}

__device__ __forceinline__ void mma16816(float* d, const uint32_t* a,
                                         uint32_t b0, uint32_t b1) {
    asm volatile(
        "mma.sync.aligned.m16n8k16.row.col.f32.f16.f16.f32 "
        "{%0,%1,%2,%3}, {%4,%5,%6,%7}, {%8,%9}, {%0,%1,%2,%3};"
        : "+f"(d[0]), "+f"(d[1]), "+f"(d[2]), "+f"(d[3])
        : "r"(a[0]), "r"(a[1]), "r"(a[2]), "r"(a[3]), "r"(b0), "r"(b1));
}

// ============================================================================
// Preprocess: W -> sign (fp16 +-1/0, exact) + per-row scale (mean |w|, fp32)
// ============================================================================
__global__ void __launch_bounds__(256)
prep_w_kernel(const float* __restrict__ w,
              __half* __restrict__ sgn,
              float* __restrict__ scale) {
    const int o = blockIdx.x;
    const int tid = threadIdx.x;
    const float4* wr = reinterpret_cast<const float4*>(w + (size_t)o * IN_F);
    __half2* sr = reinterpret_cast<__half2*>(sgn + (size_t)o * IN_F);

    const __half P1 = __float2half(1.0f);
    const __half M1 = __float2half(-1.0f);
    const __half Z0 = __float2half(0.0f);

    float acc = 0.0f;
    for (int i = tid; i < IN_F / 4; i += 256) {
        float4 v = wr[i];
        acc += fabsf(v.x) + fabsf(v.y) + fabsf(v.z) + fabsf(v.w);
        __half s0 = (v.x > 0.f) ? P1 : ((v.x < 0.f) ? M1 : Z0);
        __half s1 = (v.y > 0.f) ? P1 : ((v.y < 0.f) ? M1 : Z0);
        __half s2 = (v.z > 0.f) ? P1 : ((v.z < 0.f) ? M1 : Z0);
        __half s3 = (v.w > 0.f) ? P1 : ((v.w < 0.f) ? M1 : Z0);
        sr[2 * i]     = __halves2half2(s0, s1);
        sr[2 * i + 1] = __halves2half2(s2, s3);
    }

    __shared__ float red[256];
    red[tid] = acc;
    __syncthreads();
    #pragma unroll
    for (int off = 128; off > 0; off >>= 1) {
        if (tid < off) red[tid] += red[tid + off];
        __syncthreads();
    }
    if (tid == 0) scale[o] = red[0] * (1.0f / (float)IN_F);
}

// ============================================================================
// Preprocess: x (fp32) -> fp16 (11 mantissa bits: dot rel-err ~2.8e-4 << 1e-3)
// ============================================================================
__global__ void __launch_bounds__(256)
prep_x_kernel(const float4* __restrict__ x, __half2* __restrict__ xh) {
    size_t idx = (size_t)blockIdx.x * 256 + threadIdx.x;
    float4 v = x[idx];
    xh[2 * idx]     = __halves2half2(__float2half(v.x), __float2half(v.y));
    xh[2 * idx + 1] = __halves2half2(__float2half(v.z), __float2half(v.w));
}

// ============================================================================
// Main GEMM: out[m,n] = scale[n] * sum_k xh[m,k]*sgn[n,k] + bias[n]
//   cp.async 3-stage pipeline, SW128 XOR-swizzled smem, ldmatrix + HMMA 16816.
//   8 warps: 4(M) x 2(N); warp tile 32x64. 2 CTAs/SM for issue coverage.
// ============================================================================
__global__ void __launch_bounds__(256, 2)
hgemm_kernel(const float* __restrict__ bias, float* __restrict__ out) {
    extern __shared__ __align__(1024) char smem[];
    const uint32_t sb = smem_to_u32(smem);

    const int tid  = threadIdx.x;
    const int lane = tid & 31;
    const int warp = tid >> 5;
    const int wm = warp & 3;          // 0..3  (M strips of 32)
    const int wn = warp >> 2;         // 0..1  (N strips of 64)

    const int m0 = blockIdx.y * BM;
    const int n0 = blockIdx.x * BN;

    // ---- gmem source rows for cp.async (each thread: one 16B chunk, 4 rows)
    const int lrow = tid >> 3;        // 0..31
    const int lch  = tid & 7;         // 0..7 (16B chunk within 128B row)
    const __half* Ap = g_xh  + (size_t)m0 * IN_F;
    const __half* Bp = g_sgn + (size_t)n0 * IN_F;

    // ---- ldmatrix per-thread address components (SW128: chunk ^= row&7)
    const int rA    = lane & 15;          // A row within m16 tile
    const int halfA = lane >> 4;          // which 16B k-chunk
    const uint32_t aRowOff = (uint32_t)(wm * 32 + rA) * 128;
    const int swA = rA & 7;

    const int grp = lane >> 3;
    const int l8  = lane & 7;
    const int rB  = wn * 64 + ((grp >> 1) << 3) + l8;  // B (n) row
    const int halfB = grp & 1;
    const uint32_t bRowOff = (uint32_t)rB * 128;
    const int swB = rB & 7;

    float acc[2][8][4];
    #pragma unroll
    for (int t = 0; t < 2; t++)
        #pragma unroll
        for (int j = 0; j < 8; j++)
            #pragma unroll
            for (int r = 0; r < 4; r++) acc[t][j][r] = 0.0f;

    // ---- stage loader -------------------------------------------------------
    auto load_stage = [&](int s, int ki) {
        const int k0 = ki * BK;
        const uint32_t so = sb + (uint32_t)s * STAGE_BYTES;
        #pragma unroll
        for (int r = 0; r < 4; r++) {
            const int row = lrow + 32 * r;
            const size_t go = (size_t)row * IN_F + k0 + lch * 8;
            const uint32_t sw = (uint32_t)row * 128 +
                                (uint32_t)((lch ^ (row & 7)) << 4);
            cp_async16(so + sw,                Ap + go);
            cp_async16(so + A_TILE_BYTES + sw, Bp + go);
        }
    };

    // ---- prologue: fill STAGES-1 stages ----
    #pragma unroll
    for (int s = 0; s < STAGES - 1; s++) {
        load_stage(s, s);
        CP_COMMIT();
    }

    // ---- mainloop ----
    for (int i = 0; i < K_ITERS; i++) {
        CP_WAIT(STAGES - 2);      // stage i's group complete
        __syncthreads();          // all warps done with the stage being refilled

        const int nld = i + STAGES - 1;
        if (nld < K_ITERS) load_stage(nld % STAGES, nld);
        CP_COMMIT();

        const uint32_t so = sb + (uint32_t)(i % STAGES) * STAGE_BYTES;
        const uint32_t aA = so;
        const uint32_t bB = so + A_TILE_BYTES;

        #pragma unroll
        for (int kk = 0; kk < 4; kk++) {
            const int c = kk * 2;

            // B fragments: 4 x ldmatrix.x4 -> 8 n8-tiles of k16
            uint32_t bf[4][4];
            #pragma unroll
            for (int j = 0; j < 4; j++) {
                uint32_t addr = bB + bRowOff + (uint32_t)j * 2048 +
                                (uint32_t)(((c + halfB) ^ swB) << 4);
                ldsm4(bf[j], addr);
            }

            // A fragments: 2 m16-tiles of k16
            uint32_t af[2][4];
            {
                uint32_t sw16 = (uint32_t)(((c + halfA) ^ swA) << 4);
                ldsm4(af[0], aA + aRowOff + sw16);
                ldsm4(af[1], aA + aRowOff + 2048 + sw16);
            }

            // 16 HMMAs
            #pragma unroll
            for (int t = 0; t < 2; t++)
                #pragma unroll
                for (int j = 0; j < 4; j++) {
                    mma16816(acc[t][2 * j],     af[t], bf[j][0], bf[j][1]);
                    mma16816(acc[t][2 * j + 1], af[t], bf[j][2], bf[j][3]);
                }
        }
    }

    // ---- epilogue: y = scale[n]*acc + bias[n], float2 stores ----
    const int gm  = m0 + wm * 32 + (lane >> 2);
    const int gn0 = n0 + wn * 64 + (lane & 3) * 2;
    #pragma unroll
    for (int t = 0; t < 2; t++) {
        const int r0 = gm + t * 16;
        #pragma unroll
        for (int j = 0; j < 8; j++) {
            const int n = gn0 + j * 8;
            const float2 sc = *reinterpret_cast<const float2*>(g_scale + n);
            const float2 bi = *reinterpret_cast<const float2*>(bias + n);
            float2 v0, v1;
            v0.x = acc[t][j][0] * sc.x + bi.x;
            v0.y = acc[t][j][1] * sc.y + bi.y;
            v1.x = acc[t][j][2] * sc.x + bi.x;
            v1.y = acc[t][j][3] * sc.y + bi.y;
            *reinterpret_cast<float2*>(out + (size_t)r0 * OUT_F + n)       = v0;
            *reinterpret_cast<float2*>(out + (size_t)(r0 + 8) * OUT_F + n) = v1;
        }
    }
}

// ============================================================================
// Host side
// ============================================================================
extern "C" void kernel_launch(void* const* d_in, const int* in_sizes, int n_in,
                              void* d_out, int out_size) {
    const float* x    = (const float*)d_in[0];
    const float* w    = (const float*)d_in[1];
    const float* bias = (const float*)d_in[2];
    float* out = (float*)d_out;

    void *pxh = nullptr, *psgn = nullptr, *pscale = nullptr;
    cudaGetSymbolAddress(&pxh, g_xh);
    cudaGetSymbolAddress(&psgn, g_sgn);
    cudaGetSymbolAddress(&pscale, g_scale);

    // Preprocess
    prep_w_kernel<<<OUT_F, 256>>>(w, (__half*)psgn, (float*)pscale);
    {
        size_t n4 = ((size_t)M_TOTAL * IN_F) / 4;
        prep_x_kernel<<<(unsigned)(n4 / 256), 256>>>(
            (const float4*)x, (__half2*)pxh);
    }

    // Main GEMM
    cudaFuncSetAttribute(hgemm_kernel,
                         cudaFuncAttributeMaxDynamicSharedMemorySize, SMEM_BYTES);

    dim3 grid(OUT_F / BN, M_TOTAL / BM);   // (32, 128)
    hgemm_kernel<<<grid, 256, SMEM_BYTES>>>(bias, out);
}